// round 1
// baseline (speedup 1.0000x reference)
#include <cuda_runtime.h>
#include <math.h>

#define BATCH 65536
#define D0 784
#define D1 512
#define D2 256
#define D3 10
// descending index for threshold: round(BATCH*0.5)
#define K_DESC 32768
// ascending 0-indexed rank of that element
#define R_ASC (BATCH - 1 - K_DESC)

// ---------------- scratch (static device memory; no allocations) -------------
__device__ float g_h1[(size_t)BATCH * D1];   // 134 MB
__device__ float g_h2[(size_t)BATCH * D2];   // 67 MB
__device__ float g_h3[(size_t)BATCH * D3];
__device__ float g_h4[(size_t)BATCH * D3];
__device__ float g_norm[BATCH];
__device__ float g_mask1[BATCH];
__device__ float g_mask2[BATCH];
__device__ float g_mask3[BATCH];
__device__ float g_mask4[BATCH];

// ---------------- fp32 SGEMM: C = act(A @ W + b), optional row mask on A -----
// A: [M, K] row-major, W: [K, N] row-major, C: [M, N].
// Block tile 64x64, Ktile 16, 256 threads, 4x4 per thread.
__global__ __launch_bounds__(256)
void sgemm_bias_relu(const float* __restrict__ A, const float* __restrict__ W,
                     const float* __restrict__ bias, const float* __restrict__ mask,
                     float* __restrict__ C, int K, int N, int do_relu) {
    __shared__ float As[16][64];  // [k][m]
    __shared__ float Ws[16][64];  // [k][n]

    const int tid = threadIdx.x;
    const int tx = tid & 15;        // 0..15 -> 4 cols each
    const int ty = tid >> 4;        // 0..15 -> 4 rows each
    const int m0 = blockIdx.y * 64;
    const int n0 = blockIdx.x * 64;

    // A load mapping: 64 rows x 4 float4 along k
    const int arow = tid >> 2;      // 0..63
    const int akq  = tid & 3;       // which float4 in the 16-wide k tile
    // W load mapping: 16 k-rows x 16 float4 along n
    const int wk  = tid >> 4;       // 0..15
    const int wnq = tid & 15;       // 0..15

    const float amul = mask ? mask[m0 + arow] : 1.0f;

    float acc[4][4];
#pragma unroll
    for (int i = 0; i < 4; i++)
#pragma unroll
        for (int j = 0; j < 4; j++) acc[i][j] = 0.0f;

    for (int k0 = 0; k0 < K; k0 += 16) {
        float4 av = *reinterpret_cast<const float4*>(A + (size_t)(m0 + arow) * K + k0 + akq * 4);
        av.x *= amul; av.y *= amul; av.z *= amul; av.w *= amul;
        As[akq * 4 + 0][arow] = av.x;
        As[akq * 4 + 1][arow] = av.y;
        As[akq * 4 + 2][arow] = av.z;
        As[akq * 4 + 3][arow] = av.w;

        float4 wv = *reinterpret_cast<const float4*>(W + (size_t)(k0 + wk) * N + n0 + wnq * 4);
        *reinterpret_cast<float4*>(&Ws[wk][wnq * 4]) = wv;

        __syncthreads();

#pragma unroll
        for (int kk = 0; kk < 16; kk++) {
            float4 a = *reinterpret_cast<const float4*>(&As[kk][ty * 4]);
            float4 b = *reinterpret_cast<const float4*>(&Ws[kk][tx * 4]);
            acc[0][0] += a.x * b.x; acc[0][1] += a.x * b.y; acc[0][2] += a.x * b.z; acc[0][3] += a.x * b.w;
            acc[1][0] += a.y * b.x; acc[1][1] += a.y * b.y; acc[1][2] += a.y * b.z; acc[1][3] += a.y * b.w;
            acc[2][0] += a.z * b.x; acc[2][1] += a.z * b.y; acc[2][2] += a.z * b.z; acc[2][3] += a.z * b.w;
            acc[3][0] += a.w * b.x; acc[3][1] += a.w * b.y; acc[3][2] += a.w * b.z; acc[3][3] += a.w * b.w;
        }
        __syncthreads();
    }

    const float4 bv = *reinterpret_cast<const float4*>(bias + n0 + tx * 4);
#pragma unroll
    for (int i = 0; i < 4; i++) {
        int row = m0 + ty * 4 + i;
        float4 o;
        o.x = acc[i][0] + bv.x;
        o.y = acc[i][1] + bv.y;
        o.z = acc[i][2] + bv.z;
        o.w = acc[i][3] + bv.w;
        if (do_relu) {
            o.x = fmaxf(o.x, 0.0f); o.y = fmaxf(o.y, 0.0f);
            o.z = fmaxf(o.z, 0.0f); o.w = fmaxf(o.w, 0.0f);
        }
        *reinterpret_cast<float4*>(C + (size_t)row * N + n0 + tx * 4) = o;
    }
}

// ---------------- per-row L2 norm (warp per row) -----------------------------
__global__ void rownorm_kernel(const float* __restrict__ H, float* __restrict__ norms, int ncols) {
    int gwarp = (blockIdx.x * blockDim.x + threadIdx.x) >> 5;
    int lane = threadIdx.x & 31;
    if (gwarp >= BATCH) return;
    const float* row = H + (size_t)gwarp * ncols;
    float s = 0.0f;
    for (int c = lane; c < ncols; c += 32) { float v = row[c]; s += v * v; }
#pragma unroll
    for (int o = 16; o; o >>= 1) s += __shfl_down_sync(0xffffffffu, s, o);
    if (lane == 0) norms[gwarp] = sqrtf(s);
}

// ---------------- exact radix-select threshold + mask write ------------------
// Finds value at ascending rank R_ASC (== sorted_desc[K_DESC]) and writes
// mask = (norm > thr) to two destinations. Single block, 1024 threads.
__global__ void select_mask_kernel(const float* __restrict__ norms,
                                   float* __restrict__ mask_a, float* __restrict__ mask_b) {
    __shared__ unsigned hist[256];
    __shared__ unsigned s_prefix;
    __shared__ int s_rank;
    const int tid = threadIdx.x;
    if (tid == 0) { s_prefix = 0u; s_rank = R_ASC; }
    __syncthreads();

    for (int pass = 0; pass < 4; pass++) {
        const int shift = 24 - 8 * pass;
        for (int i = tid; i < 256; i += blockDim.x) hist[i] = 0u;
        __syncthreads();
        unsigned prefix = s_prefix;
        for (int i = tid; i < BATCH; i += blockDim.x) {
            unsigned b = __float_as_uint(norms[i]);
            bool ok = (pass == 0) || ((b >> (shift + 8)) == prefix);
            if (ok) atomicAdd(&hist[(b >> shift) & 0xffu], 1u);
        }
        __syncthreads();
        if (tid == 0) {
            int r = s_rank;
            unsigned cum = 0;
            int bin = 0;
            for (bin = 0; bin < 256; bin++) {
                if ((int)(cum + hist[bin]) > r) break;
                cum += hist[bin];
            }
            s_rank = r - (int)cum;
            s_prefix = (prefix << 8) | (unsigned)bin;
        }
        __syncthreads();
    }

    const float thr = __uint_as_float(s_prefix);
    for (int i = tid; i < BATCH; i += blockDim.x) {
        float mv = (norms[i] > thr) ? 1.0f : 0.0f;
        mask_a[i] = mv;
        mask_b[i] = mv;
    }
}

// ---------------- layer 3: [B,256] -> [B,10], relu, fused norm ---------------
__global__ __launch_bounds__(256)
void layer3_kernel(const float* __restrict__ H2, const float* __restrict__ mask2,
                   const float* __restrict__ W3, const float* __restrict__ b3,
                   float* __restrict__ H3, float* __restrict__ norms) {
    __shared__ float Ws[D2 * D3];
    __shared__ float bs[D3];
    for (int i = threadIdx.x; i < D2 * D3; i += blockDim.x) Ws[i] = W3[i];
    if (threadIdx.x < D3) bs[threadIdx.x] = b3[threadIdx.x];
    __syncthreads();

    int row = (blockIdx.x * blockDim.x + threadIdx.x) >> 5;
    int lane = threadIdx.x & 31;
    if (row >= BATCH) return;
    float m = mask2[row];
    float p[D3];
#pragma unroll
    for (int n = 0; n < D3; n++) p[n] = 0.0f;

#pragma unroll
    for (int t = 0; t < D2 / 32; t++) {
        int k = lane + 32 * t;
        float a = H2[(size_t)row * D2 + k] * m;
        const float* wrow = &Ws[k * D3];
#pragma unroll
        for (int n = 0; n < D3; n++) p[n] += a * wrow[n];
    }
#pragma unroll
    for (int o = 16; o; o >>= 1)
#pragma unroll
        for (int n = 0; n < D3; n++) p[n] += __shfl_down_sync(0xffffffffu, p[n], o);

    if (lane == 0) {
        float s = 0.0f;
#pragma unroll
        for (int n = 0; n < D3; n++) {
            float v = fmaxf(p[n] + bs[n], 0.0f);
            H3[(size_t)row * D3 + n] = v;
            s += v * v;
        }
        norms[row] = sqrtf(s);
    }
}

// ---------------- layer 4: [B,10] -> [B,10], no relu, fused norm -------------
__global__ __launch_bounds__(256)
void layer4_kernel(const float* __restrict__ H3, const float* __restrict__ mask3,
                   const float* __restrict__ W4, const float* __restrict__ b4,
                   float* __restrict__ H4, float* __restrict__ norms) {
    __shared__ float Ws[D3 * D3];
    __shared__ float bs[D3];
    if (threadIdx.x < D3 * D3) Ws[threadIdx.x] = W4[threadIdx.x];
    if (threadIdx.x < D3) bs[threadIdx.x] = b4[threadIdx.x];
    __syncthreads();

    int row = blockIdx.x * blockDim.x + threadIdx.x;
    if (row >= BATCH) return;
    float m = mask3[row];
    float a[D3];
#pragma unroll
    for (int k = 0; k < D3; k++) a[k] = H3[(size_t)row * D3 + k] * m;
    float s = 0.0f;
#pragma unroll
    for (int n = 0; n < D3; n++) {
        float v = bs[n];
#pragma unroll
        for (int k = 0; k < D3; k++) v += a[k] * Ws[k * D3 + n];
        H4[(size_t)row * D3 + n] = v;
        s += v * v;
    }
    norms[row] = sqrtf(s);
}

// ---------------- softmax over masked h4 -------------------------------------
__global__ __launch_bounds__(256)
void softmax_kernel(const float* __restrict__ H4, const float* __restrict__ mask4,
                    float* __restrict__ out) {
    int row = blockIdx.x * blockDim.x + threadIdx.x;
    if (row >= BATCH) return;
    float m = mask4[row];
    float v[D3];
    float mx = -1e30f;
#pragma unroll
    for (int n = 0; n < D3; n++) {
        v[n] = H4[(size_t)row * D3 + n] * m;
        mx = fmaxf(mx, v[n]);
    }
    float s = 0.0f;
#pragma unroll
    for (int n = 0; n < D3; n++) { v[n] = expf(v[n] - mx); s += v[n]; }
    float inv = 1.0f / s;
#pragma unroll
    for (int n = 0; n < D3; n++) out[(size_t)row * D3 + n] = v[n] * inv;
}

// ---------------- launch -----------------------------------------------------
extern "C" void kernel_launch(void* const* d_in, const int* in_sizes, int n_in,
                              void* d_out, int out_size) {
    const float* x  = (const float*)d_in[0];
    const float* W1 = (const float*)d_in[1];
    const float* b1 = (const float*)d_in[2];
    const float* W2 = (const float*)d_in[3];
    const float* b2 = (const float*)d_in[4];
    const float* W3 = (const float*)d_in[5];
    const float* b3 = (const float*)d_in[6];
    const float* W4 = (const float*)d_in[7];
    const float* b4 = (const float*)d_in[8];
    float* out = (float*)d_out;

    float *h1, *h2, *h3, *h4, *nrm, *m1, *m2, *m3, *m4;
    cudaGetSymbolAddress((void**)&h1, g_h1);
    cudaGetSymbolAddress((void**)&h2, g_h2);
    cudaGetSymbolAddress((void**)&h3, g_h3);
    cudaGetSymbolAddress((void**)&h4, g_h4);
    cudaGetSymbolAddress((void**)&nrm, g_norm);
    cudaGetSymbolAddress((void**)&m1, g_mask1);
    cudaGetSymbolAddress((void**)&m2, g_mask2);
    cudaGetSymbolAddress((void**)&m3, g_mask3);
    cudaGetSymbolAddress((void**)&m4, g_mask4);

    float* out_m1 = out + (size_t)BATCH * D3;
    float* out_m2 = out_m1 + BATCH;
    float* out_m3 = out_m2 + BATCH;
    float* out_m4 = out_m3 + BATCH;

    // Layer 1: [B,784] -> [B,512], relu
    {
        dim3 grid(D1 / 64, BATCH / 64);
        sgemm_bias_relu<<<grid, 256>>>(x, W1, b1, nullptr, h1, D0, D1, 1);
    }
    rownorm_kernel<<<(BATCH * 32) / 256, 256>>>(h1, nrm, D1);
    select_mask_kernel<<<1, 1024>>>(nrm, m1, out_m1);

    // Layer 2: [B,512] -> [B,256], relu, mask1 on input rows
    {
        dim3 grid(D2 / 64, BATCH / 64);
        sgemm_bias_relu<<<grid, 256>>>(h1, W2, b2, m1, h2, D1, D2, 1);
    }
    rownorm_kernel<<<(BATCH * 32) / 256, 256>>>(h2, nrm, D2);
    select_mask_kernel<<<1, 1024>>>(nrm, m2, out_m2);

    // Layer 3: [B,256] -> [B,10], relu, mask2 on input, fused norm
    layer3_kernel<<<(BATCH * 32) / 256, 256>>>(h2, m2, W3, b3, h3, nrm);
    select_mask_kernel<<<1, 1024>>>(nrm, m3, out_m3);

    // Layer 4: [B,10] -> [B,10], no relu, mask3 on input, fused norm
    layer4_kernel<<<BATCH / 256, 256>>>(h3, m3, W4, b4, h4, nrm);
    select_mask_kernel<<<1, 1024>>>(nrm, m4, out_m4);

    // Softmax on masked h4
    softmax_kernel<<<BATCH / 256, 256>>>(h4, m4, out);
}

// round 2
// speedup vs baseline: 1.1095x; 1.1095x over previous
#include <cuda_runtime.h>
#include <math.h>

#define BATCH 65536
#define D0 784
#define D1 512
#define D2 256
#define D3 10
// descending index for threshold: round(BATCH*0.5)
#define K_DESC 32768
// ascending 0-indexed rank of that element
#define R_ASC (BATCH - 1 - K_DESC)

// ---------------- scratch (static device memory; no allocations) -------------
__device__ float g_h1[(size_t)BATCH * D1];   // 134 MB
__device__ float g_h2[(size_t)BATCH * D2];   // 67 MB
__device__ float g_h3[(size_t)BATCH * D3];
__device__ float g_h4[(size_t)BATCH * D3];
__device__ float g_norm[BATCH];
__device__ float g_mask1[BATCH];
__device__ float g_mask2[BATCH];
__device__ float g_mask3[BATCH];
__device__ float g_mask4[BATCH];

// ---------------- fp32 SGEMM: C = relu(A @ W + b), optional row mask on A ----
// A: [M, K] row-major, W: [K, N] row-major, C: [M, N].
// Block tile 128x128, BK=8, 256 threads, 8x8 per thread, double-buffered smem.
__global__ __launch_bounds__(256)
void sgemm_bias_relu(const float* __restrict__ A, const float* __restrict__ W,
                     const float* __restrict__ bias, const float* __restrict__ mask,
                     float* __restrict__ C, int K, int N, int do_relu) {
    __shared__ float As[2][8][128];
    __shared__ float Bs[2][8][128];

    const int tid = threadIdx.x;
    const int tx = tid & 15;         // n-group 0..15
    const int ty = tid >> 4;         // m-group 0..15
    const int m0 = blockIdx.y * 128;
    const int n0 = blockIdx.x * 128;

    // A tile load mapping: 128 rows x 2 float4 along k
    const int arow = tid >> 1;       // 0..127
    const int akq  = tid & 1;        // which float4 in the 8-wide k tile
    // B tile load mapping: 8 k-rows x 32 float4 along n
    const int bk  = tid >> 5;        // 0..7
    const int bnq = tid & 31;        // 0..31

    const float amul = mask ? mask[m0 + arow] : 1.0f;
    const float* Aptr = A + (size_t)(m0 + arow) * K + akq * 4;
    const float* Bptr = W + (size_t)bk * N + n0 + bnq * 4;

    float acc[8][8];
#pragma unroll
    for (int i = 0; i < 8; i++)
#pragma unroll
        for (int j = 0; j < 8; j++) acc[i][j] = 0.0f;

    // prologue: load tile 0
    {
        float4 av = *reinterpret_cast<const float4*>(Aptr);
        av.x *= amul; av.y *= amul; av.z *= amul; av.w *= amul;
        As[0][akq * 4 + 0][arow] = av.x;
        As[0][akq * 4 + 1][arow] = av.y;
        As[0][akq * 4 + 2][arow] = av.z;
        As[0][akq * 4 + 3][arow] = av.w;
        float4 bv = *reinterpret_cast<const float4*>(Bptr);
        *reinterpret_cast<float4*>(&Bs[0][bk][bnq * 4]) = bv;
    }
    __syncthreads();

    const int ntiles = K >> 3;
    int s = 0;
#pragma unroll 1
    for (int t = 1; t < ntiles; t++) {
        // prefetch next tile into registers
        float4 av = *reinterpret_cast<const float4*>(Aptr + (size_t)t * 8);
        float4 bv = *reinterpret_cast<const float4*>(Bptr + (size_t)t * 8 * N);
        av.x *= amul; av.y *= amul; av.z *= amul; av.w *= amul;

        // compute current stage
#pragma unroll
        for (int kk = 0; kk < 8; kk++) {
            float4 a0 = *reinterpret_cast<const float4*>(&As[s][kk][ty * 4]);
            float4 a1 = *reinterpret_cast<const float4*>(&As[s][kk][64 + ty * 4]);
            float4 b0 = *reinterpret_cast<const float4*>(&Bs[s][kk][tx * 4]);
            float4 b1 = *reinterpret_cast<const float4*>(&Bs[s][kk][64 + tx * 4]);
            float am[8] = {a0.x, a0.y, a0.z, a0.w, a1.x, a1.y, a1.z, a1.w};
            float bn[8] = {b0.x, b0.y, b0.z, b0.w, b1.x, b1.y, b1.z, b1.w};
#pragma unroll
            for (int i = 0; i < 8; i++)
#pragma unroll
                for (int j = 0; j < 8; j++) acc[i][j] += am[i] * bn[j];
        }

        // store prefetched tile to other stage
        As[s ^ 1][akq * 4 + 0][arow] = av.x;
        As[s ^ 1][akq * 4 + 1][arow] = av.y;
        As[s ^ 1][akq * 4 + 2][arow] = av.z;
        As[s ^ 1][akq * 4 + 3][arow] = av.w;
        *reinterpret_cast<float4*>(&Bs[s ^ 1][bk][bnq * 4]) = bv;
        __syncthreads();
        s ^= 1;
    }

    // last tile compute
#pragma unroll
    for (int kk = 0; kk < 8; kk++) {
        float4 a0 = *reinterpret_cast<const float4*>(&As[s][kk][ty * 4]);
        float4 a1 = *reinterpret_cast<const float4*>(&As[s][kk][64 + ty * 4]);
        float4 b0 = *reinterpret_cast<const float4*>(&Bs[s][kk][tx * 4]);
        float4 b1 = *reinterpret_cast<const float4*>(&Bs[s][kk][64 + tx * 4]);
        float am[8] = {a0.x, a0.y, a0.z, a0.w, a1.x, a1.y, a1.z, a1.w};
        float bn[8] = {b0.x, b0.y, b0.z, b0.w, b1.x, b1.y, b1.z, b1.w};
#pragma unroll
        for (int i = 0; i < 8; i++)
#pragma unroll
            for (int j = 0; j < 8; j++) acc[i][j] += am[i] * bn[j];
    }

    // epilogue: bias + relu + store
    const float4 bv0 = *reinterpret_cast<const float4*>(bias + n0 + tx * 4);
    const float4 bv1 = *reinterpret_cast<const float4*>(bias + n0 + 64 + tx * 4);
#pragma unroll
    for (int i = 0; i < 8; i++) {
        int m = m0 + ((i < 4) ? (ty * 4 + i) : (64 + ty * 4 + i - 4));
        float4 o0, o1;
        o0.x = acc[i][0] + bv0.x; o0.y = acc[i][1] + bv0.y;
        o0.z = acc[i][2] + bv0.z; o0.w = acc[i][3] + bv0.w;
        o1.x = acc[i][4] + bv1.x; o1.y = acc[i][5] + bv1.y;
        o1.z = acc[i][6] + bv1.z; o1.w = acc[i][7] + bv1.w;
        if (do_relu) {
            o0.x = fmaxf(o0.x, 0.0f); o0.y = fmaxf(o0.y, 0.0f);
            o0.z = fmaxf(o0.z, 0.0f); o0.w = fmaxf(o0.w, 0.0f);
            o1.x = fmaxf(o1.x, 0.0f); o1.y = fmaxf(o1.y, 0.0f);
            o1.z = fmaxf(o1.z, 0.0f); o1.w = fmaxf(o1.w, 0.0f);
        }
        *reinterpret_cast<float4*>(C + (size_t)m * N + n0 + tx * 4) = o0;
        *reinterpret_cast<float4*>(C + (size_t)m * N + n0 + 64 + tx * 4) = o1;
    }
}

// ---------------- per-row L2 norm (warp per row, float4) ---------------------
__global__ void rownorm_kernel(const float* __restrict__ H, float* __restrict__ norms, int ncols) {
    int gwarp = (blockIdx.x * blockDim.x + threadIdx.x) >> 5;
    int lane = threadIdx.x & 31;
    if (gwarp >= BATCH) return;
    const float4* row = reinterpret_cast<const float4*>(H + (size_t)gwarp * ncols);
    const int n4 = ncols >> 2;
    float s = 0.0f;
    for (int c = lane; c < n4; c += 32) {
        float4 v = row[c];
        s += v.x * v.x + v.y * v.y + v.z * v.z + v.w * v.w;
    }
#pragma unroll
    for (int o = 16; o; o >>= 1) s += __shfl_down_sync(0xffffffffu, s, o);
    if (lane == 0) norms[gwarp] = sqrtf(s);
}

// ---------------- exact radix-select threshold + mask write ------------------
__global__ void select_mask_kernel(const float* __restrict__ norms,
                                   float* __restrict__ mask_a, float* __restrict__ mask_b) {
    __shared__ unsigned hist[256];
    __shared__ unsigned s_prefix;
    __shared__ int s_rank;
    const int tid = threadIdx.x;
    if (tid == 0) { s_prefix = 0u; s_rank = R_ASC; }
    __syncthreads();

    for (int pass = 0; pass < 4; pass++) {
        const int shift = 24 - 8 * pass;
        for (int i = tid; i < 256; i += blockDim.x) hist[i] = 0u;
        __syncthreads();
        unsigned prefix = s_prefix;
        for (int i = tid; i < BATCH; i += blockDim.x) {
            unsigned b = __float_as_uint(norms[i]);
            bool ok = (pass == 0) || ((b >> (shift + 8)) == prefix);
            if (ok) atomicAdd(&hist[(b >> shift) & 0xffu], 1u);
        }
        __syncthreads();
        if (tid == 0) {
            int r = s_rank;
            unsigned cum = 0;
            int bin = 0;
            for (bin = 0; bin < 256; bin++) {
                if ((int)(cum + hist[bin]) > r) break;
                cum += hist[bin];
            }
            s_rank = r - (int)cum;
            s_prefix = (prefix << 8) | (unsigned)bin;
        }
        __syncthreads();
    }

    const float thr = __uint_as_float(s_prefix);
    for (int i = tid; i < BATCH; i += blockDim.x) {
        float mv = (norms[i] > thr) ? 1.0f : 0.0f;
        mask_a[i] = mv;
        mask_b[i] = mv;
    }
}

// ---------------- layer 3: [B,256] -> [B,10], relu, fused norm ---------------
__global__ __launch_bounds__(256)
void layer3_kernel(const float* __restrict__ H2, const float* __restrict__ mask2,
                   const float* __restrict__ W3, const float* __restrict__ b3,
                   float* __restrict__ H3, float* __restrict__ norms) {
    __shared__ float Ws[D2 * D3];
    __shared__ float bs[D3];
    for (int i = threadIdx.x; i < D2 * D3; i += blockDim.x) Ws[i] = W3[i];
    if (threadIdx.x < D3) bs[threadIdx.x] = b3[threadIdx.x];
    __syncthreads();

    int row = (blockIdx.x * blockDim.x + threadIdx.x) >> 5;
    int lane = threadIdx.x & 31;
    if (row >= BATCH) return;
    float m = mask2[row];
    float p[D3];
#pragma unroll
    for (int n = 0; n < D3; n++) p[n] = 0.0f;

#pragma unroll
    for (int t = 0; t < D2 / 32; t++) {
        int k = lane + 32 * t;
        float a = H2[(size_t)row * D2 + k] * m;
        const float* wrow = &Ws[k * D3];
#pragma unroll
        for (int n = 0; n < D3; n++) p[n] += a * wrow[n];
    }
#pragma unroll
    for (int o = 16; o; o >>= 1)
#pragma unroll
        for (int n = 0; n < D3; n++) p[n] += __shfl_down_sync(0xffffffffu, p[n], o);

    if (lane == 0) {
        float s = 0.0f;
#pragma unroll
        for (int n = 0; n < D3; n++) {
            float v = fmaxf(p[n] + bs[n], 0.0f);
            H3[(size_t)row * D3 + n] = v;
            s += v * v;
        }
        norms[row] = sqrtf(s);
    }
}

// ---------------- layer 4: [B,10] -> [B,10], no relu, fused norm -------------
__global__ __launch_bounds__(256)
void layer4_kernel(const float* __restrict__ H3, const float* __restrict__ mask3,
                   const float* __restrict__ W4, const float* __restrict__ b4,
                   float* __restrict__ H4, float* __restrict__ norms) {
    __shared__ float Ws[D3 * D3];
    __shared__ float bs[D3];
    if (threadIdx.x < D3 * D3) Ws[threadIdx.x] = W4[threadIdx.x];
    if (threadIdx.x < D3) bs[threadIdx.x] = b4[threadIdx.x];
    __syncthreads();

    int row = blockIdx.x * blockDim.x + threadIdx.x;
    if (row >= BATCH) return;
    float m = mask3[row];
    float a[D3];
#pragma unroll
    for (int k = 0; k < D3; k++) a[k] = H3[(size_t)row * D3 + k] * m;
    float s = 0.0f;
#pragma unroll
    for (int n = 0; n < D3; n++) {
        float v = bs[n];
#pragma unroll
        for (int k = 0; k < D3; k++) v += a[k] * Ws[k * D3 + n];
        H4[(size_t)row * D3 + n] = v;
        s += v * v;
    }
    norms[row] = sqrtf(s);
}

// ---------------- softmax over masked h4 -------------------------------------
__global__ __launch_bounds__(256)
void softmax_kernel(const float* __restrict__ H4, const float* __restrict__ mask4,
                    float* __restrict__ out) {
    int row = blockIdx.x * blockDim.x + threadIdx.x;
    if (row >= BATCH) return;
    float m = mask4[row];
    float v[D3];
    float mx = -1e30f;
#pragma unroll
    for (int n = 0; n < D3; n++) {
        v[n] = H4[(size_t)row * D3 + n] * m;
        mx = fmaxf(mx, v[n]);
    }
    float s = 0.0f;
#pragma unroll
    for (int n = 0; n < D3; n++) { v[n] = expf(v[n] - mx); s += v[n]; }
    float inv = 1.0f / s;
#pragma unroll
    for (int n = 0; n < D3; n++) out[(size_t)row * D3 + n] = v[n] * inv;
}

// ---------------- launch -----------------------------------------------------
extern "C" void kernel_launch(void* const* d_in, const int* in_sizes, int n_in,
                              void* d_out, int out_size) {
    const float* x  = (const float*)d_in[0];
    const float* W1 = (const float*)d_in[1];
    const float* b1 = (const float*)d_in[2];
    const float* W2 = (const float*)d_in[3];
    const float* b2 = (const float*)d_in[4];
    const float* W3 = (const float*)d_in[5];
    const float* b3 = (const float*)d_in[6];
    const float* W4 = (const float*)d_in[7];
    const float* b4 = (const float*)d_in[8];
    float* out = (float*)d_out;

    float *h1, *h2, *h3, *h4, *nrm, *m1, *m2, *m3, *m4;
    cudaGetSymbolAddress((void**)&h1, g_h1);
    cudaGetSymbolAddress((void**)&h2, g_h2);
    cudaGetSymbolAddress((void**)&h3, g_h3);
    cudaGetSymbolAddress((void**)&h4, g_h4);
    cudaGetSymbolAddress((void**)&nrm, g_norm);
    cudaGetSymbolAddress((void**)&m1, g_mask1);
    cudaGetSymbolAddress((void**)&m2, g_mask2);
    cudaGetSymbolAddress((void**)&m3, g_mask3);
    cudaGetSymbolAddress((void**)&m4, g_mask4);

    float* out_m1 = out + (size_t)BATCH * D3;
    float* out_m2 = out_m1 + BATCH;
    float* out_m3 = out_m2 + BATCH;
    float* out_m4 = out_m3 + BATCH;

    // Layer 1: [B,784] -> [B,512], relu   (784 = 98 * 8)
    {
        dim3 grid(D1 / 128, BATCH / 128);
        sgemm_bias_relu<<<grid, 256>>>(x, W1, b1, nullptr, h1, D0, D1, 1);
    }
    rownorm_kernel<<<(BATCH * 32) / 256, 256>>>(h1, nrm, D1);
    select_mask_kernel<<<1, 1024>>>(nrm, m1, out_m1);

    // Layer 2: [B,512] -> [B,256], relu, mask1 on input rows
    {
        dim3 grid(D2 / 128, BATCH / 128);
        sgemm_bias_relu<<<grid, 256>>>(h1, W2, b2, m1, h2, D1, D2, 1);
    }
    rownorm_kernel<<<(BATCH * 32) / 256, 256>>>(h2, nrm, D2);
    select_mask_kernel<<<1, 1024>>>(nrm, m2, out_m2);

    // Layer 3: [B,256] -> [B,10], relu, mask2 on input, fused norm
    layer3_kernel<<<(BATCH * 32) / 256, 256>>>(h2, m2, W3, b3, h3, nrm);
    select_mask_kernel<<<1, 1024>>>(nrm, m3, out_m3);

    // Layer 4: [B,10] -> [B,10], no relu, mask3 on input, fused norm
    layer4_kernel<<<BATCH / 256, 256>>>(h3, m3, W4, b4, h4, nrm);
    select_mask_kernel<<<1, 1024>>>(nrm, m4, out_m4);

    // Softmax on masked h4
    softmax_kernel<<<BATCH / 256, 256>>>(h4, m4, out);
}